// round 2
// baseline (speedup 1.0000x reference)
#include <cuda_runtime.h>

// Problem constants
#define BATCH 64
#define DDIM  4096
#define SDIM  128          // slice size S
#define NTOK  256          // 2S
#define KT    32           // K-chunk for GEMM

// n^2 - n with n = 256
#define NN_MINUS_N 65280.0f

// Scratch (static __device__, no allocations)
__device__ float g_sq[BATCH * NTOK];   // per-batch squared norms of each token
__device__ float g_bwA[BATCH];         // per-batch  sum(L2) = 2n*sum(sq) - 2*||sum x||^2
__device__ float g_part[BATCH * 3];    // per-CTA signed kernel partial sums

// ---------------------------------------------------------------------------
// K1: stats. One CTA per batch, 8 warps. Warp w handles d = w, w+8, ...
// For each d: lane loads float4 of source[d][4*lane..] and target[d][4*lane..]
// (fully coalesced 512B per tensor per d). Computes per-i sq partials and the
// per-d (row-sum)^2 term for the bandwidth. Deterministic (fixed-order smem
// reduction, direct stores, no atomics).
// ---------------------------------------------------------------------------
__global__ __launch_bounds__(256) void stats_kernel(const float* __restrict__ src,
                                                    const float* __restrict__ tgt)
{
    int b    = blockIdx.x;
    int warp = threadIdx.x >> 5;
    int lane = threadIdx.x & 31;

    const float4* sb = (const float4*)(src + (size_t)b * DDIM * SDIM);
    const float4* tb = (const float4*)(tgt + (size_t)b * DDIM * SDIM);

    float sqloc[8];
#pragma unroll
    for (int q = 0; q < 8; q++) sqloc[q] = 0.0f;
    float accA = 0.0f;

    for (int d = warp; d < DDIM; d += 8) {
        float4 vs = sb[d * 32 + lane];
        float4 vt = tb[d * 32 + lane];
        float v[8] = {vs.x, vs.y, vs.z, vs.w, vt.x, vt.y, vt.z, vt.w};
        float s1 = 0.0f, s2 = 0.0f;
#pragma unroll
        for (int q = 0; q < 8; q++) {
            s1 += v[q];
            float p = v[q] * v[q];
            s2 += p;
            sqloc[q] += p;
        }
#pragma unroll
        for (int o = 16; o; o >>= 1) {
            s1 += __shfl_xor_sync(0xffffffffu, s1, o);
            s2 += __shfl_xor_sync(0xffffffffu, s2, o);
        }
        if (lane == 0) accA += 2.0f * (float)NTOK * s2 - 2.0f * s1 * s1;
    }

    __shared__ float ssq[8][NTOK];
    __shared__ float sA[8];
#pragma unroll
    for (int q = 0; q < 8; q++) {
        int i = (q < 4) ? (4 * lane + q) : (SDIM + 4 * lane + (q - 4));
        ssq[warp][i] = sqloc[q];
    }
    if (lane == 0) sA[warp] = accA;
    __syncthreads();

    {
        int i = threadIdx.x;                 // 256 threads -> 256 tokens
        float s = 0.0f;
#pragma unroll
        for (int wq = 0; wq < 8; wq++) s += ssq[wq][i];
        g_sq[b * NTOK + i] = s;
    }
    if (threadIdx.x == 0) {
        float A = 0.0f;
#pragma unroll
        for (int wq = 0; wq < 8; wq++) A += sA[wq];
        g_bwA[b] = A;
    }
}

// ---------------------------------------------------------------------------
// K2: fused 128x128x4096 Gram tile + MMD epilogue.
// blockIdx.x = tile (0: ss, 1: st [x2 weight], 2: tt), blockIdx.y = batch.
// 256 threads, 8x8 microtile per thread, KT=32 smem chunks.
// ---------------------------------------------------------------------------
__global__ __launch_bounds__(256) void gram_mmd_kernel(const float* __restrict__ src,
                                                       const float* __restrict__ tgt)
{
    __shared__ float As[KT][128];
    __shared__ float Bs[KT][128];

    int tile = blockIdx.x;
    int b    = blockIdx.y;

    int   i0 = (tile == 2) ? SDIM : 0;
    int   j0 = (tile == 0) ? 0 : SDIM;
    float w  = (tile == 1) ? -2.0f : 1.0f;

    const float* Abase = ((i0 == 0) ? src : tgt) + (size_t)b * DDIM * SDIM;
    const float* Bbase = ((j0 == 0) ? src : tgt) + (size_t)b * DDIM * SDIM;

    int t  = threadIdx.x;
    int ty = t >> 4;     // 0..15 -> rows ty*8 .. ty*8+7
    int tx = t & 15;     // 0..15 -> cols tx*8 .. tx*8+7

    float acc[8][8];
#pragma unroll
    for (int u = 0; u < 8; u++)
#pragma unroll
        for (int v = 0; v < 8; v++) acc[u][v] = 0.0f;

    for (int d0 = 0; d0 < DDIM; d0 += KT) {
        // Load KT x 128 of each operand (coalesced: consecutive threads ->
        // consecutive tokens within a d-row).
#pragma unroll
        for (int p = 0; p < 16; p++) {
            int l  = t + p * 256;        // 0..4095
            int dd = l >> 7;
            int ii = l & 127;
            As[dd][ii] = Abase[(size_t)(d0 + dd) * SDIM + ii];
            Bs[dd][ii] = Bbase[(size_t)(d0 + dd) * SDIM + ii];
        }
        __syncthreads();

#pragma unroll
        for (int k = 0; k < KT; k++) {
            float a[8], bb[8];
            *(float4*)&a[0]  = *(const float4*)&As[k][ty * 8];
            *(float4*)&a[4]  = *(const float4*)&As[k][ty * 8 + 4];
            *(float4*)&bb[0] = *(const float4*)&Bs[k][tx * 8];
            *(float4*)&bb[4] = *(const float4*)&Bs[k][tx * 8 + 4];
#pragma unroll
            for (int u = 0; u < 8; u++)
#pragma unroll
                for (int v = 0; v < 8; v++) acc[u][v] += a[u] * bb[v];
        }
        __syncthreads();
    }

    // ---- fused MMD epilogue ----
    // bw = sum(L2)/(n^2-n) / kernel_mul^(num//2);  bws_k = bw * 2^k, k=0..4
    float bw = g_bwA[b] * (1.0f / NN_MINUS_N) * 0.25f;
    float nk[5];
#pragma unroll
    for (int k = 0; k < 5; k++) nk[k] = -1.0f / (bw * (float)(1 << k));

    const float* sqp = &g_sq[b * NTOK];
    float sqi[8], sqj[8];
#pragma unroll
    for (int u = 0; u < 8; u++) sqi[u] = sqp[i0 + ty * 8 + u];
#pragma unroll
    for (int v = 0; v < 8; v++) sqj[v] = sqp[j0 + tx * 8 + v];

    float psum = 0.0f;
#pragma unroll
    for (int u = 0; u < 8; u++) {
#pragma unroll
        for (int v = 0; v < 8; v++) {
            float L2 = sqi[u] + sqj[v] - 2.0f * acc[u][v];
            float e  = 0.0f;
#pragma unroll
            for (int k = 0; k < 5; k++) e += __expf(L2 * nk[k]);
            psum += e;
        }
    }
    psum *= w;

    // deterministic block reduction
    __shared__ float red[256];
    red[t] = psum;
    __syncthreads();
#pragma unroll
    for (int s = 128; s > 0; s >>= 1) {
        if (t < s) red[t] += red[t + s];
        __syncthreads();
    }
    if (t == 0) g_part[b * 3 + tile] = red[0];
}

// ---------------------------------------------------------------------------
// K3: deterministic finalize of 192 partials -> loss scalar.
// loss = total / (S*S) / B
// ---------------------------------------------------------------------------
__global__ void finalize_kernel(float* __restrict__ out)
{
    __shared__ float red[256];
    int t = threadIdx.x;
    red[t] = (t < BATCH * 3) ? g_part[t] : 0.0f;
    __syncthreads();
#pragma unroll
    for (int s = 128; s > 0; s >>= 1) {
        if (t < s) red[t] += red[t + s];
        __syncthreads();
    }
    if (t == 0) out[0] = red[0] * (1.0f / ((float)SDIM * (float)SDIM * (float)BATCH));
}

extern "C" void kernel_launch(void* const* d_in, const int* in_sizes, int n_in,
                              void* d_out, int out_size)
{
    const float* src = (const float*)d_in[0];
    const float* tgt = (const float*)d_in[1];
    float* out = (float*)d_out;

    stats_kernel<<<BATCH, 256>>>(src, tgt);
    gram_mmd_kernel<<<dim3(3, BATCH), 256>>>(src, tgt);
    finalize_kernel<<<1, 256>>>(out);
}

// round 5
// speedup vs baseline: 2.3194x; 2.3194x over previous
#include <cuda_runtime.h>
#include <cstdint>

// Problem constants
#define BATCH 64
#define DDIM  4096
#define SDIM  128
#define NTOK  256
#define NCHUNK 128             // D / 32
#define NN_MINUS_N 65280.0f    // n^2-n, n=256

#define ROWF  136              // padded floats per smem row (bank-conflict-free)
#define ROWB  (ROWF * 4)       // 544 bytes
#define TILEB (32 * ROWB)      // 17408 bytes per operand tile
#define STGB  (2 * TILEB)      // 34816 bytes per stage (A + B)

// Scratch
__device__ float g_sq[BATCH * NTOK];
__device__ float g_bwA[BATCH];
__device__ float g_sq_part[BATCH * 8 * NTOK];
__device__ float g_bwA_part[BATCH * 8];
__device__ float g_part[BATCH * 3];

static __device__ __forceinline__ uint32_t smem_u32(const void* p) {
    uint32_t a;
    asm("{ .reg .u64 t; cvta.to.shared.u64 t, %1; cvt.u32.u64 %0, t; }" : "=r"(a) : "l"(p));
    return a;
}
static __device__ __forceinline__ void cp16(uint32_t dst, const void* src) {
    asm volatile("cp.async.ca.shared.global [%0], [%1], 16;" :: "r"(dst), "l"(src) : "memory");
}
static __device__ __forceinline__ void mma_tf32(float* c, const uint32_t* a, const uint32_t* b) {
    asm volatile(
        "mma.sync.aligned.m16n8k8.row.col.f32.tf32.tf32.f32 "
        "{%0,%1,%2,%3}, {%4,%5,%6,%7}, {%8,%9}, {%0,%1,%2,%3};"
        : "+f"(c[0]), "+f"(c[1]), "+f"(c[2]), "+f"(c[3])
        : "r"(a[0]), "r"(a[1]), "r"(a[2]), "r"(a[3]), "r"(b[0]), "r"(b[1]));
}
// 3xTF32 split: x = hi + lo (both tf32-representable)
static __device__ __forceinline__ void split_tf32(float x, uint32_t& hi, uint32_t& lo) {
    asm("cvt.rna.tf32.f32 %0, %1;" : "=r"(hi) : "f"(x));
    float l = x - __uint_as_float(hi);
    asm("cvt.rna.tf32.f32 %0, %1;" : "=r"(lo) : "f"(l));
}

// ---------------------------------------------------------------------------
// K1: stats partials. grid (8 segs, 64 batches), 512 d-rows per CTA.
// ---------------------------------------------------------------------------
__global__ __launch_bounds__(256) void stats_part(const float* __restrict__ src,
                                                  const float* __restrict__ tgt)
{
    int seg = blockIdx.x, b = blockIdx.y;
    int warp = threadIdx.x >> 5, lane = threadIdx.x & 31;

    const float4* sb = (const float4*)(src + (size_t)b * DDIM * SDIM);
    const float4* tb = (const float4*)(tgt + (size_t)b * DDIM * SDIM);

    float sqloc[8];
#pragma unroll
    for (int q = 0; q < 8; q++) sqloc[q] = 0.0f;
    float accA = 0.0f;

#pragma unroll 4
    for (int it = 0; it < 64; it++) {
        int d = seg * 512 + it * 8 + warp;
        float4 vs = sb[d * 32 + lane];
        float4 vt = tb[d * 32 + lane];
        float v[8] = {vs.x, vs.y, vs.z, vs.w, vt.x, vt.y, vt.z, vt.w};
        float s1 = 0.0f, s2 = 0.0f;
#pragma unroll
        for (int q = 0; q < 8; q++) {
            s1 += v[q];
            float p = v[q] * v[q];
            s2 += p;
            sqloc[q] += p;
        }
#pragma unroll
        for (int o = 16; o; o >>= 1) {
            s1 += __shfl_xor_sync(0xffffffffu, s1, o);
            s2 += __shfl_xor_sync(0xffffffffu, s2, o);
        }
        if (lane == 0) accA += 2.0f * (float)NTOK * s2 - 2.0f * s1 * s1;
    }

    __shared__ float ssq[8][NTOK];
    __shared__ float sA[8];
#pragma unroll
    for (int q = 0; q < 8; q++) {
        int i = (q < 4) ? (4 * lane + q) : (SDIM + 4 * lane + (q - 4));
        ssq[warp][i] = sqloc[q];
    }
    if (lane == 0) sA[warp] = accA;
    __syncthreads();

    {
        int i = threadIdx.x;
        float s = 0.0f;
#pragma unroll
        for (int wq = 0; wq < 8; wq++) s += ssq[wq][i];
        g_sq_part[(size_t)(b * 8 + seg) * NTOK + i] = s;
    }
    if (threadIdx.x == 0) {
        float A = 0.0f;
#pragma unroll
        for (int wq = 0; wq < 8; wq++) A += sA[wq];
        g_bwA_part[b * 8 + seg] = A;
    }
}

__global__ void stats_combine()
{
    int b = blockIdx.x, t = threadIdx.x;
    float s = 0.0f;
#pragma unroll
    for (int seg = 0; seg < 8; seg++) s += g_sq_part[(size_t)(b * 8 + seg) * NTOK + t];
    g_sq[b * NTOK + t] = s;
    if (t == 0) {
        float A = 0.0f;
#pragma unroll
        for (int seg = 0; seg < 8; seg++) A += g_bwA_part[b * 8 + seg];
        g_bwA[b] = A;
    }
}

// ---------------------------------------------------------------------------
// K2: 3xTF32 mma.sync Gram (128x128x4096) + fused MMD epilogue.
// blockIdx.x = tile (0 ss, 1 st x-2, 2 tt), blockIdx.y = batch.
// 8 warps, warp (wm=w&3, wn=w>>2) owns rows wm*32..+31, cols wn*64..+63.
// ---------------------------------------------------------------------------
extern __shared__ char dynsmem[];

static __device__ __forceinline__ void load_stage(uint32_t stb, const char* A,
                                                  const char* B, bool dual,
                                                  int d0, int t)
{
#pragma unroll
    for (int p = 0; p < 4; p++) {
        int s   = t + (p << 8);
        int row = s >> 5;
        int off = (s & 31) << 4;
        cp16(stb + row * ROWB + off, A + (size_t)(d0 + row) * 512 + off);
    }
    if (dual) {
#pragma unroll
        for (int p = 0; p < 4; p++) {
            int s   = t + (p << 8);
            int row = s >> 5;
            int off = (s & 31) << 4;
            cp16(stb + TILEB + row * ROWB + off, B + (size_t)(d0 + row) * 512 + off);
        }
    }
}

__global__ __launch_bounds__(256, 2) void gram_mmd_mma(const float* __restrict__ src,
                                                       const float* __restrict__ tgt)
{
    const int tile = blockIdx.x;
    const int b    = blockIdx.y;
    const int t    = threadIdx.x;
    const int wid  = t >> 5;
    const int lid  = t & 31;
    const int gid  = lid >> 2;   // 0..7
    const int kq   = lid & 3;    // 0..3
    const int wm   = wid & 3;    // row block
    const int wn   = wid >> 2;   // col block

    const int   i0 = (tile == 2) ? SDIM : 0;
    const int   j0 = (tile == 0) ? 0 : SDIM;
    const float w  = (tile == 1) ? -2.0f : 1.0f;
    const bool  dual = (tile == 1);

    const char* Abase = (const char*)(((i0 == 0) ? src : tgt) + (size_t)b * DDIM * SDIM);
    const char* Bbase = (const char*)(((j0 == 0) ? src : tgt) + (size_t)b * DDIM * SDIM);

    __shared__ float red[256];
    __shared__ float sq_sh[NTOK];
    sq_sh[t] = g_sq[b * NTOK + t];

    const uint32_t sb = smem_u32(dynsmem);

    float acc[2][8][4];
#pragma unroll
    for (int mt = 0; mt < 2; mt++)
#pragma unroll
        for (int nt = 0; nt < 8; nt++)
#pragma unroll
            for (int r = 0; r < 4; r++) acc[mt][nt][r] = 0.0f;

    // prologue
    load_stage(sb, Abase, Bbase, dual, 0, t);
    asm volatile("cp.async.commit_group;" ::: "memory");

    for (int c = 0; c < NCHUNK; c++) {
        if (c + 1 < NCHUNK) {
            load_stage(sb + ((c + 1) & 1) * STGB, Abase, Bbase, dual, (c + 1) * 32, t);
            asm volatile("cp.async.commit_group;" ::: "memory");
            asm volatile("cp.async.wait_group 1;" ::: "memory");
        } else {
            asm volatile("cp.async.wait_group 0;" ::: "memory");
        }
        __syncthreads();

        const float* As = (const float*)(dynsmem + (c & 1) * STGB);
        const float* Bs = dual ? (const float*)(dynsmem + (c & 1) * STGB + TILEB) : As;

#pragma unroll
        for (int kk = 0; kk < 4; kk++) {
            const float* r0 = As + (kk * 8 + kq) * ROWF;
            const float* r1 = As + (kk * 8 + kq + 4) * ROWF;
            const float* q0 = Bs + (kk * 8 + kq) * ROWF;
            const float* q1 = Bs + (kk * 8 + kq + 4) * ROWF;

            // A fragments: split into hi/lo, reused across all 8 n-tiles
            uint32_t ah[2][4], al[2][4];
#pragma unroll
            for (int mt = 0; mt < 2; mt++) {
                int m = wm * 32 + mt * 16 + gid;
                split_tf32(r0[m],     ah[mt][0], al[mt][0]);
                split_tf32(r0[m + 8], ah[mt][1], al[mt][1]);
                split_tf32(r1[m],     ah[mt][2], al[mt][2]);
                split_tf32(r1[m + 8], ah[mt][3], al[mt][3]);
            }

            // B fragments in two halves of 4 n-tiles (register pressure)
#pragma unroll
            for (int nh = 0; nh < 2; nh++) {
                uint32_t bh[4][2], bl[4][2];
#pragma unroll
                for (int nt = 0; nt < 4; nt++) {
                    int n = wn * 64 + (nh * 4 + nt) * 8 + gid;
                    split_tf32(q0[n], bh[nt][0], bl[nt][0]);
                    split_tf32(q1[n], bh[nt][1], bl[nt][1]);
                }
#pragma unroll
                for (int mt = 0; mt < 2; mt++)
#pragma unroll
                    for (int nt = 0; nt < 4; nt++) {
                        float* a = acc[mt][nh * 4 + nt];
                        mma_tf32(a, ah[mt], bh[nt]);   // hi*hi
                        mma_tf32(a, ah[mt], bl[nt]);   // hi*lo
                        mma_tf32(a, al[mt], bh[nt]);   // lo*hi
                    }
            }
        }
        __syncthreads();
    }

    // ---- fused MMD epilogue ----
    float bw = g_bwA[b] * (1.0f / NN_MINUS_N) * 0.25f;
    float c4 = -1.0f / (16.0f * bw);

    float psum = 0.0f;
#pragma unroll
    for (int mt = 0; mt < 2; mt++) {
        float si0 = sq_sh[i0 + wm * 32 + mt * 16 + gid];
        float si1 = sq_sh[i0 + wm * 32 + mt * 16 + gid + 8];
#pragma unroll
        for (int nt = 0; nt < 8; nt++) {
            float sj0 = sq_sh[j0 + wn * 64 + nt * 8 + 2 * kq];
            float sj1 = sq_sh[j0 + wn * 64 + nt * 8 + 2 * kq + 1];
#pragma unroll
            for (int r = 0; r < 4; r++) {
                float si = (r < 2) ? si0 : si1;
                float sj = (r & 1) ? sj1 : sj0;
                float L2 = si + sj - 2.0f * acc[mt][nt][r];
                float e1 = __expf(L2 * c4);
                float e2 = e1 * e1, e4 = e2 * e2, e8 = e4 * e4, e16 = e8 * e8;
                psum += e1 + e2 + e4 + e8 + e16;
            }
        }
    }

    red[t] = psum;
    __syncthreads();
#pragma unroll
    for (int s = 128; s > 0; s >>= 1) {
        if (t < s) red[t] += red[t + s];
        __syncthreads();
    }
    if (t == 0) g_part[b * 3 + tile] = red[0] * w;
}

// ---------------------------------------------------------------------------
// K3: finalize
// ---------------------------------------------------------------------------
__global__ void finalize_kernel(float* __restrict__ out)
{
    __shared__ float red[256];
    int t = threadIdx.x;
    red[t] = (t < BATCH * 3) ? g_part[t] : 0.0f;
    __syncthreads();
#pragma unroll
    for (int s = 128; s > 0; s >>= 1) {
        if (t < s) red[t] += red[t + s];
        __syncthreads();
    }
    if (t == 0) out[0] = red[0] * (1.0f / ((float)SDIM * (float)SDIM * (float)BATCH));
}

extern "C" void kernel_launch(void* const* d_in, const int* in_sizes, int n_in,
                              void* d_out, int out_size)
{
    const float* src = (const float*)d_in[0];
    const float* tgt = (const float*)d_in[1];
    float* out = (float*)d_out;

    static bool configured = false;
    if (!configured) {
        cudaFuncSetAttribute(gram_mmd_mma, cudaFuncAttributeMaxDynamicSharedMemorySize, 2 * STGB);
        configured = true;
    }

    stats_part<<<dim3(8, BATCH), 256>>>(src, tgt);
    stats_combine<<<BATCH, 256>>>();
    gram_mmd_mma<<<dim3(3, BATCH), 256, 2 * STGB>>>(src, tgt);
    finalize_kernel<<<1, 256>>>(out);
}